// round 9
// baseline (speedup 1.0000x reference)
#include <cuda_runtime.h>
#include <cuda_fp16.h>
#include <math.h>
#include <stdint.h>

// Problem constants
#define NB   8192
#define NC   200
#define NK   16
#define ND   512
#define NCK  3200
#define K2   1024
#define D_LOG_2PI 940.9930579935848f

// ---------------- scratch (device globals) ----------------
__device__ __half g_Ah[NB * K2];
__device__ __half g_Al[NB * K2];
__device__ __half g_Bh[NCK * K2];
__device__ __half g_Bl[NCK * K2];
__device__ float  g_bias[NCK];
__device__ float  g_logw[NCK];
__device__ float  g_logp[NC];
__device__ float  g_main[(size_t)NB * NCK];   // Ah*Bh partial (105 MB)
__device__ __half g_corr[(size_t)NB * NCK];   // AhBl+AlBh partial (52 MB)

// ---------------- helpers ----------------
__device__ __forceinline__ uint32_t smem_u32(const void* p) {
    uint32_t a;
    asm("{ .reg .u64 t; cvta.to.shared.u64 t, %1; cvt.u32.u64 %0, t; }" : "=r"(a) : "l"(p));
    return a;
}
__device__ __forceinline__ uint32_t swz(uint32_t o) {   // SW128 over 128B rows
    return o ^ (((o >> 7) & 7) << 4);
}
__device__ __forceinline__ void cp16(uint32_t saddr, const void* gaddr) {
    asm volatile("cp.async.cg.shared.global [%0], [%1], 16;" :: "r"(saddr), "l"(gaddr));
}
__device__ __forceinline__ void ldsm4(uint32_t* r, uint32_t addr) {
    asm volatile("ldmatrix.sync.aligned.m8n8.x4.shared.b16 {%0,%1,%2,%3}, [%4];"
        : "=r"(r[0]), "=r"(r[1]), "=r"(r[2]), "=r"(r[3]) : "r"(addr));
}
__device__ __forceinline__ void mma4_f32(float* c, const uint32_t* a, uint32_t b0, uint32_t b1) {
    asm("mma.sync.aligned.m16n8k16.row.col.f32.f16.f16.f32 "
        "{%0,%1,%2,%3}, {%4,%5,%6,%7}, {%8,%9}, {%0,%1,%2,%3};"
        : "+f"(c[0]), "+f"(c[1]), "+f"(c[2]), "+f"(c[3])
        : "r"(a[0]), "r"(a[1]), "r"(a[2]), "r"(a[3]), "r"(b0), "r"(b1));
}
__device__ __forceinline__ void mma2_f16(uint32_t* c, const uint32_t* a, uint32_t b0, uint32_t b1) {
    asm("mma.sync.aligned.m16n8k16.row.col.f16.f16.f16.f16 "
        "{%0,%1}, {%2,%3,%4,%5}, {%6,%7}, {%0,%1};"
        : "+r"(c[0]), "+r"(c[1])
        : "r"(a[0]), "r"(a[1]), "r"(a[2]), "r"(a[3]), "r"(b0), "r"(b1));
}

// ---------------- prep kernels ----------------
__global__ void prep_x_kernel(const float* __restrict__ x) {
    int i = blockIdx.x * blockDim.x + threadIdx.x;
    if (i < NB * ND) {
        int b = i >> 9, d = i & 511;
        float v = x[i];
        float a = v * v;
        __half h = __float2half_rn(a);
        g_Ah[b * K2 + d] = h;
        g_Al[b * K2 + d] = __float2half_rn(a - __half2float(h));
        __half h2 = __float2half_rn(v);
        g_Ah[b * K2 + ND + d] = h2;
        g_Al[b * K2 + ND + d] = __float2half_rn(v - __half2float(h2));
    }
}

__global__ void prep_wp_kernel(const float* __restrict__ weights,
                               const float* __restrict__ priors) {
    __shared__ float sh[256];
    int t = threadIdx.x;
    if (t < NC) {
        float wv[NK];
        float m = -1e30f;
        #pragma unroll
        for (int k = 0; k < NK; k++) { wv[k] = weights[t * NK + k]; m = fmaxf(m, wv[k]); }
        float s = 0.f;
        #pragma unroll
        for (int k = 0; k < NK; k++) s += expf(wv[k] - m);
        float inv_s = 1.f / s;
        #pragma unroll
        for (int k = 0; k < NK; k++)
            g_logw[t * NK + k] = logf(expf(wv[k] - m) * inv_s + 1e-6f);
    }
    float pv = (t < NC) ? priors[t] : -1e30f;
    sh[t] = pv;
    __syncthreads();
    for (int s = 128; s > 0; s >>= 1) { if (t < s) sh[t] = fmaxf(sh[t], sh[t + s]); __syncthreads(); }
    float M = sh[0];
    __syncthreads();
    float e = (t < NC) ? expf(pv - M) : 0.f;
    sh[t] = e;
    __syncthreads();
    for (int s = 128; s > 0; s >>= 1) { if (t < s) sh[t] += sh[t + s]; __syncthreads(); }
    float S = sh[0];
    if (t < NC) g_logp[t] = logf(e / S + 1e-6f);
}

__global__ void prep_comp_kernel(const float* __restrict__ means,
                                 const float* __restrict__ bw) {
    int j = blockIdx.x;
    int t = threadIdx.x;   // 128
    float ld = 0.f, cj = 0.f;
    #pragma unroll
    for (int d = t; d < ND; d += 128) {
        float bv = bw[j * ND + d];
        bv = fminf(fmaxf(bv, 1e-6f), 1000.f);
        float inv = 1.0f / bv;
        float mu  = means[j * ND + d];
        float m2  = -2.0f * mu * inv;
        __half h = __float2half_rn(inv);
        g_Bh[j * K2 + d] = h;
        g_Bl[j * K2 + d] = __float2half_rn(inv - __half2float(h));
        __half h2 = __float2half_rn(m2);
        g_Bh[j * K2 + ND + d] = h2;
        g_Bl[j * K2 + ND + d] = __float2half_rn(m2 - __half2float(h2));
        ld += logf(bv);
        cj += mu * mu * inv;
    }
    __shared__ float shd[128], shc[128];
    shd[t] = ld; shc[t] = cj;
    __syncthreads();
    for (int s = 64; s > 0; s >>= 1) {
        if (t < s) { shd[t] += shd[t + s]; shc[t] += shc[t + s]; }
        __syncthreads();
    }
    if (t == 0)
        g_bias[j] = -0.5f * (D_LOG_2PI + shd[0] + shc[0]) + g_logw[j];
}

// ================= G1: main pass Ah*Bh, f32 acc =================
// BM=128 BN=128 BK=64, 3 stages of 32KB, 8 warps (2m x 4n), warp 64x32
#define G1_STAGE 32768
#define G1_NST 3
#define G1_SMEM (G1_NST * G1_STAGE)

__global__ void __launch_bounds__(256, 2) gemm_main_kernel() {
    extern __shared__ char smem[];
    uint32_t sb = smem_u32(smem);
    int tid = threadIdx.x;
    int wid = tid >> 5, lane = tid & 31;
    int rowBase = blockIdx.y * 128;
    int colBase = blockIdx.x * 128;

    int wm = (wid & 1) * 64;
    int wn = (wid >> 1) * 32;
    int lrow = lane & 15;
    uint32_t lcol = (uint32_t)((lane >> 4) * 16);

    // loaders: A 128 rows x 8 chunks (1024 cp16), B same -> 4 iters each
    const __half* pA[4]; uint32_t sA[4];
    const __half* pB[4]; uint32_t sB[4];
    #pragma unroll
    for (int it = 0; it < 4; it++) {
        int idx = tid + it * 256;
        int row = idx >> 3, ch = idx & 7;
        pA[it] = g_Ah + (size_t)(rowBase + row) * K2 + ch * 8;
        sA[it] = swz((uint32_t)(row * 128 + ch * 16));
        pB[it] = g_Bh + (size_t)(colBase + row) * K2 + ch * 8;
        sB[it] = sA[it];
    }

    uint32_t baseA[4], baseB[2];
    #pragma unroll
    for (int mi = 0; mi < 4; mi++) {
        int r = wm + mi * 16 + lrow;
        baseA[mi] = sb + (uint32_t)(r * 128 + ((r & 7) << 4));
    }
    #pragma unroll
    for (int nj = 0; nj < 2; nj++) {
        int r = wn + nj * 16 + lrow;
        baseB[nj] = sb + 16384 + (uint32_t)(r * 128 + ((r & 7) << 4));
    }

    float acc[64];
    #pragma unroll
    for (int i = 0; i < 64; i++) acc[i] = 0.f;

    auto load_stage = [&](int st, int k0) {
        uint32_t sa = sb + st * G1_STAGE;
        #pragma unroll
        for (int it = 0; it < 4; it++) {
            cp16(sa + sA[it],          pA[it] + k0);
            cp16(sa + 16384 + sB[it],  pB[it] + k0);
        }
        asm volatile("cp.async.commit_group;" ::: "memory");
    };

    load_stage(0, 0);
    load_stage(1, 64);

    int st = 0;
    for (int s = 0; s < 16; s++) {
        if (s < 14) asm volatile("cp.async.wait_group 1;" ::: "memory");
        else        asm volatile("cp.async.wait_group 0;" ::: "memory");
        __syncthreads();

        uint32_t so = (uint32_t)st * G1_STAGE;
        if (s + 2 < 16) {
            int nst = st + 2; if (nst >= G1_NST) nst -= G1_NST;
            load_stage(nst, (s + 2) * 64);
        }

        #pragma unroll
        for (int ks = 0; ks < 4; ks++) {
            uint32_t kb = (uint32_t)(ks * 32) + lcol;
            uint32_t bh0[4], bh1[4];
            ldsm4(bh0, (baseB[0] + so) ^ kb);
            ldsm4(bh1, (baseB[1] + so) ^ kb);
            #pragma unroll
            for (int mi = 0; mi < 4; mi++) {
                float* C = &acc[mi * 16];
                uint32_t ah[4];
                ldsm4(ah, (baseA[mi] + so) ^ kb);
                mma4_f32(C + 0,  ah, bh0[0], bh0[2]);
                mma4_f32(C + 4,  ah, bh0[1], bh0[3]);
                mma4_f32(C + 8,  ah, bh1[0], bh1[2]);
                mma4_f32(C + 12, ah, bh1[1], bh1[3]);
            }
        }
        st++; if (st >= G1_NST) st = 0;
    }

    // epilogue: direct global float2 stores
    #pragma unroll
    for (int mi = 0; mi < 4; mi++)
        #pragma unroll
        for (int nj = 0; nj < 4; nj++) {
            float* a = &acc[(mi * 4 + nj) * 4];
            int r0 = rowBase + wm + mi * 16 + (lane >> 2);
            int c  = colBase + wn + nj * 8 + 2 * (lane & 3);
            *(float2*)&g_main[(size_t)r0 * NCK + c]       = make_float2(a[0], a[1]);
            *(float2*)&g_main[(size_t)(r0 + 8) * NCK + c] = make_float2(a[2], a[3]);
        }
}

// ================= G2: corrections AhBl + AlBh, f16 acc =================
// BM=256 BN=128 BK=32 (hi/lo packed per 128B row), 2 stages of 48KB,
// 8 warps (4m x 2n), warp 64x64
#define G2_STAGE 49152
#define G2_NST 2
#define G2_SMEM (G2_NST * G2_STAGE)

__global__ void __launch_bounds__(256, 2) gemm_corr_kernel() {
    extern __shared__ char smem[];
    uint32_t sb = smem_u32(smem);
    int tid = threadIdx.x;
    int wid = tid >> 5, lane = tid & 31;
    int rowBase = blockIdx.y * 256;
    int colBase = blockIdx.x * 128;

    int wm = (wid & 3) * 64;
    int wn = (wid >> 2) * 64;
    int lrow = lane & 15;
    uint32_t lcol = (uint32_t)((lane >> 4) * 16);

    // loaders: A 256 rows x 8 chunks (2048 cp16 -> 8 iters); B 128 x 8 (4 iters)
    const __half* pA[8]; uint32_t sA[8];
    const __half* pB[4]; uint32_t sB[4];
    #pragma unroll
    for (int it = 0; it < 8; it++) {
        int idx = tid + it * 256;
        int row = idx >> 3, ch = idx & 7;
        pA[it] = (ch < 4 ? g_Ah : g_Al) + (size_t)(rowBase + row) * K2 + (ch & 3) * 8;
        sA[it] = swz((uint32_t)(row * 128 + ch * 16));
    }
    #pragma unroll
    for (int it = 0; it < 4; it++) {
        int idx = tid + it * 256;
        int row = idx >> 3, ch = idx & 7;
        pB[it] = (ch < 4 ? g_Bh : g_Bl) + (size_t)(colBase + row) * K2 + (ch & 3) * 8;
        sB[it] = swz((uint32_t)(row * 128 + ch * 16));
    }

    uint32_t baseA[4], baseB[4];
    #pragma unroll
    for (int mi = 0; mi < 4; mi++) {
        int r = wm + mi * 16 + lrow;
        baseA[mi] = sb + (uint32_t)(r * 128 + ((r & 7) << 4));
    }
    #pragma unroll
    for (int nj = 0; nj < 4; nj++) {
        int r = wn + nj * 16 + lrow;
        baseB[nj] = sb + 32768 + (uint32_t)(r * 128 + ((r & 7) << 4));
    }

    uint32_t cacc[64];   // 4 mi x 8 nblk x 2 regs (f16x2)
    #pragma unroll
    for (int i = 0; i < 64; i++) cacc[i] = 0u;

    auto load_stage = [&](int st, int k0) {
        uint32_t sa = sb + st * G2_STAGE;
        #pragma unroll
        for (int it = 0; it < 8; it++) cp16(sa + sA[it], pA[it] + k0);
        #pragma unroll
        for (int it = 0; it < 4; it++) cp16(sa + 32768 + sB[it], pB[it] + k0);
        asm volatile("cp.async.commit_group;" ::: "memory");
    };

    load_stage(0, 0);

    int st = 0;
    for (int s = 0; s < 32; s++) {
        asm volatile("cp.async.wait_group 0;" ::: "memory");
        __syncthreads();

        uint32_t so = (uint32_t)st * G2_STAGE;
        if (s + 1 < 32) {
            load_stage(st ^ 1, (s + 1) * 32);
        }

        #pragma unroll
        for (int ks = 0; ks < 2; ks++) {
            uint32_t kb = (uint32_t)(ks * 32) + lcol;   // hi cols
            uint32_t kl = kb + 64u;                     // lo cols

            uint32_t bh[4][4], bl[4][4];
            #pragma unroll
            for (int nj = 0; nj < 4; nj++) {
                ldsm4(bh[nj], (baseB[nj] + so) ^ kb);
                ldsm4(bl[nj], (baseB[nj] + so) ^ kl);
            }

            #pragma unroll
            for (int mi = 0; mi < 4; mi++) {
                uint32_t ah[4], al[4];
                ldsm4(ah, (baseA[mi] + so) ^ kb);
                ldsm4(al, (baseA[mi] + so) ^ kl);
                #pragma unroll
                for (int nb = 0; nb < 8; nb++) {
                    uint32_t* D = &cacc[(mi * 8 + nb) * 2];
                    int nj = nb >> 1, pr = nb & 1;
                    mma2_f16(D, ah, bl[nj][pr], bl[nj][pr + 2]);
                    mma2_f16(D, al, bh[nj][pr], bh[nj][pr + 2]);
                }
            }
        }
        st ^= 1;
    }

    // epilogue: direct global half2 stores
    #pragma unroll
    for (int mi = 0; mi < 4; mi++)
        #pragma unroll
        for (int nb = 0; nb < 8; nb++) {
            uint32_t* d = &cacc[(mi * 8 + nb) * 2];
            int r0 = rowBase + wm + mi * 16 + (lane >> 2);
            int c  = colBase + wn + nb * 8 + 2 * (lane & 3);
            *(uint32_t*)&g_corr[(size_t)r0 * NCK + c]       = d[0];
            *(uint32_t*)&g_corr[(size_t)(r0 + 8) * NCK + c] = d[1];
        }
}

// ================= combine: v=-0.5*(main+corr)+bias; lse over K; normalize =================
__global__ void combine_kernel(float* __restrict__ out) {
    __shared__ float sh[256];
    size_t row = blockIdx.x;
    int t = threadIdx.x;

    float lc = -1e30f;
    if (t < NC) {
        const float4* pm = (const float4*)&g_main[row * NCK + t * NK];
        const uint4*  pc = (const uint4*)&g_corr[row * NCK + t * NK];
        const float4* pb = (const float4*)&g_bias[t * NK];
        float v[16];
        #pragma unroll
        for (int q = 0; q < 4; q++) {
            float4 m = pm[q];
            float4 b = pb[q];
            v[q * 4 + 0] = fmaf(-0.5f, m.x, b.x);
            v[q * 4 + 1] = fmaf(-0.5f, m.y, b.y);
            v[q * 4 + 2] = fmaf(-0.5f, m.z, b.z);
            v[q * 4 + 3] = fmaf(-0.5f, m.w, b.w);
        }
        #pragma unroll
        for (int q = 0; q < 2; q++) {
            uint4 cw = pc[q];
            float2 c0 = __half22float2(*(__half2*)&cw.x);
            float2 c1 = __half22float2(*(__half2*)&cw.y);
            float2 c2 = __half22float2(*(__half2*)&cw.z);
            float2 c3 = __half22float2(*(__half2*)&cw.w);
            v[q * 8 + 0] += -0.5f * c0.x;  v[q * 8 + 1] += -0.5f * c0.y;
            v[q * 8 + 2] += -0.5f * c1.x;  v[q * 8 + 3] += -0.5f * c1.y;
            v[q * 8 + 4] += -0.5f * c2.x;  v[q * 8 + 5] += -0.5f * c2.y;
            v[q * 8 + 6] += -0.5f * c3.x;  v[q * 8 + 7] += -0.5f * c3.y;
        }
        float m = v[0];
        #pragma unroll
        for (int j = 1; j < 16; j++) m = fmaxf(m, v[j]);
        float s = 0.f;
        #pragma unroll
        for (int j = 0; j < 16; j++) s += __expf(v[j] - m);
        lc = m + __logf(s) + g_logp[t];
    }

    sh[t] = lc;
    __syncthreads();
    for (int s = 128; s > 0; s >>= 1) { if (t < s) sh[t] = fmaxf(sh[t], sh[t + s]); __syncthreads(); }
    float M = sh[0];
    __syncthreads();
    sh[t] = (t < NC) ? __expf(lc - M) : 0.f;
    __syncthreads();
    for (int s = 128; s > 0; s >>= 1) { if (t < s) sh[t] += sh[t + s]; __syncthreads(); }
    float lse = M + __logf(sh[0]);
    if (t < NC) out[row * NC + t] = lc - lse;
}

// ---------------- launch ----------------
extern "C" void kernel_launch(void* const* d_in, const int* in_sizes, int n_in,
                              void* d_out, int out_size) {
    const float* x       = (const float*)d_in[0];
    const float* means   = (const float*)d_in[1];
    const float* bw      = (const float*)d_in[2];
    const float* weights = (const float*)d_in[3];
    const float* priors  = (const float*)d_in[4];
    float* out = (float*)d_out;

    cudaFuncSetAttribute(gemm_main_kernel, cudaFuncAttributeMaxDynamicSharedMemorySize, G1_SMEM);
    cudaFuncSetAttribute(gemm_corr_kernel, cudaFuncAttributeMaxDynamicSharedMemorySize, G2_SMEM);

    prep_x_kernel<<<(NB * ND + 255) / 256, 256>>>(x);
    prep_wp_kernel<<<1, 256>>>(weights, priors);
    prep_comp_kernel<<<NCK, 128>>>(means, bw);

    dim3 g1(NCK / 128, NB / 128);   // (25, 64)
    gemm_main_kernel<<<g1, 256, G1_SMEM>>>();

    dim3 g2(NCK / 128, NB / 256);   // (25, 32)
    gemm_corr_kernel<<<g2, 256, G2_SMEM>>>();

    combine_kernel<<<NB, 256>>>(out);
}

// round 11
// speedup vs baseline: 1.1606x; 1.1606x over previous
#include <cuda_runtime.h>
#include <cuda_bf16.h>
#include <math.h>
#include <stdint.h>

// Problem constants
#define NB   8192
#define NC   200
#define NK   16
#define ND   512
#define NCK  3200
#define K2   1024          // 2*ND concatenated GEMM K
#define D_LOG_2PI 940.9930579935848f

// GEMM tiling (R6 champion config)
#define BM 128
#define BN 128
#define BK 32              // K elems per stage; hi/lo packed in one 128B row
#define NSTEPS (K2/BK)     // 32
#define NTHR 256
#define NSTAGE 3

#define STAGE_BYTES 32768
#define BIAS_OFF    (NSTAGE * STAGE_BYTES)          // bias AFTER stages
#define SMEM_TOTAL  (BIAS_OFF + 512)
#define CPAD 136

// ---------------- scratch (device globals) ----------------
__device__ __nv_bfloat16 g_Ah[NB * K2];
__device__ __nv_bfloat16 g_Al[NB * K2];
__device__ __nv_bfloat16 g_Bh[NCK * K2];
__device__ __nv_bfloat16 g_Bl[NCK * K2];
__device__ float g_bias[NCK];
__device__ float g_logw[NCK];
__device__ float g_logp[NC];
__device__ float g_cls[NB * NC];

// ---------------- helpers ----------------
__device__ __forceinline__ uint32_t smem_u32(const void* p) {
    uint32_t a;
    asm("{ .reg .u64 t; cvta.to.shared.u64 t, %1; cvt.u32.u64 %0, t; }" : "=r"(a) : "l"(p));
    return a;
}
__device__ __forceinline__ uint32_t swz(uint32_t o) {   // SW128 over 128B rows
    return o ^ (((o >> 7) & 7) << 4);
}
__device__ __forceinline__ void cp16(uint32_t saddr, const void* gaddr) {
    asm volatile("cp.async.cg.shared.global [%0], [%1], 16;" :: "r"(saddr), "l"(gaddr));
}
__device__ __forceinline__ void ldsm4(uint32_t* r, uint32_t addr) {
    asm volatile("ldmatrix.sync.aligned.m8n8.x4.shared.b16 {%0,%1,%2,%3}, [%4];"
        : "=r"(r[0]), "=r"(r[1]), "=r"(r[2]), "=r"(r[3]) : "r"(addr));
}
__device__ __forceinline__ void mma4(float* c, const uint32_t* a, uint32_t b0, uint32_t b1) {
    asm("mma.sync.aligned.m16n8k16.row.col.f32.bf16.bf16.f32 "
        "{%0,%1,%2,%3}, {%4,%5,%6,%7}, {%8,%9}, {%0,%1,%2,%3};"
        : "+f"(c[0]), "+f"(c[1]), "+f"(c[2]), "+f"(c[3])
        : "r"(a[0]), "r"(a[1]), "r"(a[2]), "r"(a[3]), "r"(b0), "r"(b1));
}

// ---------------- prep: A' = [x^2 | x] hi/lo, vectorized ----------------
__global__ void prep_x_kernel(const float* __restrict__ x) {
    int i = blockIdx.x * blockDim.x + threadIdx.x;   // over NB*ND/4
    if (i < NB * ND / 4) {
        int b = i >> 7;              // 128 float4-groups per row
        int d4 = (i & 127) * 4;
        float4 v = *(const float4*)(x + (size_t)b * ND + d4);
        float vv[4] = {v.x, v.y, v.z, v.w};
        __nv_bfloat16 h[4], l[4], h2[4], l2[4];
        #pragma unroll
        for (int q = 0; q < 4; q++) {
            float a = vv[q] * vv[q];
            h[q] = __float2bfloat16(a);
            l[q] = __float2bfloat16(a - __bfloat162float(h[q]));
            h2[q] = __float2bfloat16(vv[q]);
            l2[q] = __float2bfloat16(vv[q] - __bfloat162float(h2[q]));
        }
        size_t base = (size_t)b * K2 + d4;
        *(__nv_bfloat162*)(g_Ah + base)     = __nv_bfloat162(h[0], h[1]);
        *(__nv_bfloat162*)(g_Ah + base + 2) = __nv_bfloat162(h[2], h[3]);
        *(__nv_bfloat162*)(g_Al + base)     = __nv_bfloat162(l[0], l[1]);
        *(__nv_bfloat162*)(g_Al + base + 2) = __nv_bfloat162(l[2], l[3]);
        size_t base2 = base + ND;
        *(__nv_bfloat162*)(g_Ah + base2)     = __nv_bfloat162(h2[0], h2[1]);
        *(__nv_bfloat162*)(g_Ah + base2 + 2) = __nv_bfloat162(h2[2], h2[3]);
        *(__nv_bfloat162*)(g_Al + base2)     = __nv_bfloat162(l2[0], l2[1]);
        *(__nv_bfloat162*)(g_Al + base2 + 2) = __nv_bfloat162(l2[2], l2[3]);
    }
}

// ---------------- prep: weight softmax + prior softmax ----------------
__global__ void prep_wp_kernel(const float* __restrict__ weights,
                               const float* __restrict__ priors) {
    __shared__ float sh[256];
    int t = threadIdx.x;
    if (t < NC) {
        float wv[NK];
        float m = -1e30f;
        #pragma unroll
        for (int k = 0; k < NK; k++) { wv[k] = weights[t * NK + k]; m = fmaxf(m, wv[k]); }
        float s = 0.f;
        #pragma unroll
        for (int k = 0; k < NK; k++) s += expf(wv[k] - m);
        float inv_s = 1.f / s;
        #pragma unroll
        for (int k = 0; k < NK; k++)
            g_logw[t * NK + k] = logf(expf(wv[k] - m) * inv_s + 1e-6f);
    }
    float pv = (t < NC) ? priors[t] : -1e30f;
    sh[t] = pv;
    __syncthreads();
    for (int s = 128; s > 0; s >>= 1) { if (t < s) sh[t] = fmaxf(sh[t], sh[t + s]); __syncthreads(); }
    float M = sh[0];
    __syncthreads();
    float e = (t < NC) ? expf(pv - M) : 0.f;
    sh[t] = e;
    __syncthreads();
    for (int s = 128; s > 0; s >>= 1) { if (t < s) sh[t] += sh[t + s]; __syncthreads(); }
    float S = sh[0];
    if (t < NC) g_logp[t] = logf(e / S + 1e-6f);
}

// ---------------- prep: B' hi/lo + bias, vectorized x4 ----------------
__global__ void prep_comp_kernel(const float* __restrict__ means,
                                 const float* __restrict__ bw) {
    int j = blockIdx.x;
    int t = threadIdx.x;   // 128 threads, 4 d's each
    int d4 = t * 4;
    float4 bv4 = *(const float4*)(bw + (size_t)j * ND + d4);
    float4 mu4 = *(const float4*)(means + (size_t)j * ND + d4);
    float bvv[4] = {bv4.x, bv4.y, bv4.z, bv4.w};
    float muv[4] = {mu4.x, mu4.y, mu4.z, mu4.w};
    float ld = 0.f, cj = 0.f;
    __nv_bfloat16 bh[4], bl[4], mh[4], ml[4];
    #pragma unroll
    for (int q = 0; q < 4; q++) {
        float bv = fminf(fmaxf(bvv[q], 1e-6f), 1000.f);
        float inv = 1.0f / bv;
        float m2  = -2.0f * muv[q] * inv;
        bh[q] = __float2bfloat16(inv);
        bl[q] = __float2bfloat16(inv - __bfloat162float(bh[q]));
        mh[q] = __float2bfloat16(m2);
        ml[q] = __float2bfloat16(m2 - __bfloat162float(mh[q]));
        ld += logf(bv);
        cj += muv[q] * muv[q] * inv;
    }
    size_t base = (size_t)j * K2 + d4;
    *(__nv_bfloat162*)(g_Bh + base)     = __nv_bfloat162(bh[0], bh[1]);
    *(__nv_bfloat162*)(g_Bh + base + 2) = __nv_bfloat162(bh[2], bh[3]);
    *(__nv_bfloat162*)(g_Bl + base)     = __nv_bfloat162(bl[0], bl[1]);
    *(__nv_bfloat162*)(g_Bl + base + 2) = __nv_bfloat162(bl[2], bl[3]);
    size_t base2 = base + ND;
    *(__nv_bfloat162*)(g_Bh + base2)     = __nv_bfloat162(mh[0], mh[1]);
    *(__nv_bfloat162*)(g_Bh + base2 + 2) = __nv_bfloat162(mh[2], mh[3]);
    *(__nv_bfloat162*)(g_Bl + base2)     = __nv_bfloat162(ml[0], ml[1]);
    *(__nv_bfloat162*)(g_Bl + base2 + 2) = __nv_bfloat162(ml[2], ml[3]);

    // warp-shuffle + smem reduction over 128 threads
    #pragma unroll
    for (int o = 16; o > 0; o >>= 1) {
        ld += __shfl_down_sync(0xffffffff, ld, o);
        cj += __shfl_down_sync(0xffffffff, cj, o);
    }
    __shared__ float shd[4], shc[4];
    if ((t & 31) == 0) { shd[t >> 5] = ld; shc[t >> 5] = cj; }
    __syncthreads();
    if (t == 0) {
        float LD = shd[0] + shd[1] + shd[2] + shd[3];
        float CJ = shc[0] + shc[1] + shc[2] + shc[3];
        g_bias[j] = -0.5f * (D_LOG_2PI + LD + CJ) + g_logw[j];
    }
}

// ---------------- main GEMM (R6 champion, bf16x3, 2 CTAs/SM) ----------------
__global__ void __launch_bounds__(NTHR, 2) gemm_kernel() {
    extern __shared__ char smem[];
    uint32_t sb = smem_u32(smem);
    int tid = threadIdx.x;
    int wid = tid >> 5, lane = tid & 31;
    int rowBase = blockIdx.y * BM;
    int colBase = blockIdx.x * BN;
    float* bias_sm = (float*)(smem + BIAS_OFF);     // AFTER stage buffers

    if (tid < 128) bias_sm[tid] = g_bias[colBase + tid];

    // 8 warps = 2(m) x 4(n); warp tile 64m x 32n
    int wm = (wid & 1) * 64;
    int wn = (wid >> 1) * 32;
    int lrow = lane & 15;
    uint32_t lcol = (uint32_t)((lane >> 4) * 16);

    // per-thread cp.async source pointers (bumped per stage) + smem offsets
    const __nv_bfloat16* pA[4]; uint32_t sA[4];
    const __nv_bfloat16* pB[4]; uint32_t sB[4];
    #pragma unroll
    for (int it = 0; it < 4; it++) {
        int idx = tid + it * NTHR;             // 0..1023
        int row = idx >> 3, ch = idx & 7;
        uint32_t goff = (uint32_t)((rowBase + row) * K2 + (ch & 3) * 8);
        pA[it] = (ch < 4 ? g_Ah : g_Al) + goff;
        sA[it] = swz((uint32_t)(row * 128 + ch * 16));
        uint32_t goffB = (uint32_t)((colBase + row) * K2 + (ch & 3) * 8);
        pB[it] = (ch < 4 ? g_Bh : g_Bl) + goffB;
        sB[it] = swz((uint32_t)(row * 128 + ch * 16));
    }

    // ldmatrix base addresses (col swizzle folded; addr = base ^ colbytes)
    uint32_t baseA[4], baseB[2];
    #pragma unroll
    for (int mi = 0; mi < 4; mi++) {
        int r = wm + mi * 16 + lrow;
        baseA[mi] = sb + (uint32_t)(r * 128 + ((r & 7) << 4));
    }
    #pragma unroll
    for (int nj = 0; nj < 2; nj++) {
        int r = wn + nj * 16 + lrow;
        baseB[nj] = sb + 16384 + (uint32_t)(r * 128 + ((r & 7) << 4));
    }

    float acc[64];
    #pragma unroll
    for (int i = 0; i < 64; i++) acc[i] = 0.f;

    // stage loader: pointer-bump (no k0 adds); stages at smem offset 0
    auto load_stage = [&](int st) {
        uint32_t sa = sb + (uint32_t)st * STAGE_BYTES;
        #pragma unroll
        for (int it = 0; it < 4; it++) {
            cp16(sa + sA[it],          pA[it]);
            cp16(sa + 16384 + sB[it],  pB[it]);
            pA[it] += BK;
            pB[it] += BK;
        }
        asm volatile("cp.async.commit_group;" ::: "memory");
    };

    load_stage(0);
    load_stage(1);

    int st = 0;
    for (int s = 0; s < NSTEPS; s++) {
        if (s < NSTEPS - 2)
            asm volatile("cp.async.wait_group 1;" ::: "memory");
        else
            asm volatile("cp.async.wait_group 0;" ::: "memory");
        __syncthreads();

        uint32_t so = (uint32_t)st * STAGE_BYTES;

        if (s + 2 < NSTEPS) {
            int nst = st + 2; if (nst >= NSTAGE) nst -= NSTAGE;
            load_stage(nst);
        }

        #pragma unroll
        for (int ks = 0; ks < 2; ks++) {
            uint32_t kb = (uint32_t)(ks * 32) + lcol;   // hi cols
            uint32_t kl = kb + 64u;                     // lo cols

            uint32_t bh0[4], bh1[4], bl0[4], bl1[4];
            ldsm4(bh0, (baseB[0] + so) ^ kb);
            ldsm4(bh1, (baseB[1] + so) ^ kb);
            ldsm4(bl0, (baseB[0] + so) ^ kl);
            ldsm4(bl1, (baseB[1] + so) ^ kl);

            #pragma unroll
            for (int mi = 0; mi < 4; mi++) {
                float* C = &acc[mi * 16];
                uint32_t ah[4], al[4];
                ldsm4(ah, (baseA[mi] + so) ^ kb);
                mma4(C + 0,  ah, bh0[0], bh0[2]);
                mma4(C + 4,  ah, bh0[1], bh0[3]);
                mma4(C + 8,  ah, bh1[0], bh1[2]);
                mma4(C + 12, ah, bh1[1], bh1[3]);
                ldsm4(al, (baseA[mi] + so) ^ kl);
                mma4(C + 0,  ah, bl0[0], bl0[2]);
                mma4(C + 4,  ah, bl0[1], bl0[3]);
                mma4(C + 8,  ah, bl1[0], bl1[2]);
                mma4(C + 12, ah, bl1[1], bl1[3]);
                mma4(C + 0,  al, bh0[0], bh0[2]);
                mma4(C + 4,  al, bh0[1], bh0[3]);
                mma4(C + 8,  al, bh1[0], bh1[2]);
                mma4(C + 12, al, bh1[1], bh1[3]);
            }
        }
        st++; if (st >= NSTAGE) st = 0;
    }
    __syncthreads();    // all ldsm done before reusing smem as C staging

    // ---- epilogue: stage C to smem (offset 0; bias untouched), fused lse ----
    float* csh = (float*)smem;
    #pragma unroll
    for (int mi = 0; mi < 4; mi++)
        #pragma unroll
        for (int nj = 0; nj < 4; nj++) {
            float* a = &acc[(mi * 4 + nj) * 4];
            int r0 = wm + mi * 16 + (lane >> 2);
            int c0 = wn + nj * 8 + 2 * (lane & 3);
            csh[r0 * CPAD + c0]           = a[0];
            csh[r0 * CPAD + c0 + 1]       = a[1];
            csh[(r0 + 8) * CPAD + c0]     = a[2];
            csh[(r0 + 8) * CPAD + c0 + 1] = a[3];
        }
    __syncthreads();

    #pragma unroll
    for (int i = 0; i < 4; i++) {
        int p = tid + i * NTHR;      // 0..1023: 128 rows x 8 classes
        int row = p >> 3, cl = p & 7;
        const float* base = &csh[row * CPAD + cl * 16];
        float4 x0 = *(const float4*)(base + 0);
        float4 x1 = *(const float4*)(base + 4);
        float4 x2 = *(const float4*)(base + 8);
        float4 x3 = *(const float4*)(base + 12);
        float v[16] = {x0.x, x0.y, x0.z, x0.w, x1.x, x1.y, x1.z, x1.w,
                       x2.x, x2.y, x2.z, x2.w, x3.x, x3.y, x3.z, x3.w};
        #pragma unroll
        for (int j = 0; j < 16; j++)
            v[j] = fmaf(-0.5f, v[j], bias_sm[cl * 16 + j]);
        float m = v[0];
        #pragma unroll
        for (int j = 1; j < 16; j++) m = fmaxf(m, v[j]);
        float sum = 0.f;
        #pragma unroll
        for (int j = 0; j < 16; j++) sum += __expf(v[j] - m);
        g_cls[(size_t)(rowBase + row) * NC + (colBase >> 4) + cl] = m + __logf(sum);
    }
}

// ---------------- per-row reduction over classes ----------------
__global__ void reduce_kernel(float* __restrict__ out) {
    __shared__ float sh[256];
    size_t row = blockIdx.x;
    int t = threadIdx.x;
    float lc = -1e30f;
    if (t < NC) lc = g_cls[row * NC + t] + g_logp[t];
    sh[t] = lc;
    __syncthreads();
    for (int s = 128; s > 0; s >>= 1) { if (t < s) sh[t] = fmaxf(sh[t], sh[t + s]); __syncthreads(); }
    float M = sh[0];
    __syncthreads();
    sh[t] = (t < NC) ? __expf(lc - M) : 0.f;
    __syncthreads();
    for (int s = 128; s > 0; s >>= 1) { if (t < s) sh[t] += sh[t + s]; __syncthreads(); }
    float lse = M + __logf(sh[0]);
    if (t < NC) out[row * NC + t] = lc - lse;
}

// ---------------- launch ----------------
extern "C" void kernel_launch(void* const* d_in, const int* in_sizes, int n_in,
                              void* d_out, int out_size) {
    const float* x       = (const float*)d_in[0];
    const float* means   = (const float*)d_in[1];
    const float* bw      = (const float*)d_in[2];
    const float* weights = (const float*)d_in[3];
    const float* priors  = (const float*)d_in[4];
    float* out = (float*)d_out;

    cudaFuncSetAttribute(gemm_kernel, cudaFuncAttributeMaxDynamicSharedMemorySize, SMEM_TOTAL);

    prep_x_kernel<<<(NB * ND / 4 + 255) / 256, 256>>>(x);
    prep_wp_kernel<<<1, 256>>>(weights, priors);
    prep_comp_kernel<<<NCK, 128>>>(means, bw);

    dim3 grid(NCK / BN, NB / BM);   // (25, 64)
    gemm_kernel<<<grid, NTHR, SMEM_TOTAL>>>();

    reduce_kernel<<<NB, 256>>>(out);
}

// round 12
// speedup vs baseline: 1.1752x; 1.0126x over previous
#include <cuda_runtime.h>
#include <cuda_bf16.h>
#include <math.h>
#include <stdint.h>

// Problem constants
#define NB   8192
#define NC   200
#define NK   16
#define ND   512
#define NCK  3200
#define K2   1024          // 2*ND concatenated GEMM K
#define D_LOG_2PI 940.9930579935848f

// GEMM tiling (R6/R11 champion config)
#define BM 128
#define BN 128
#define BK 32
#define NSTEPS (K2/BK)     // 32
#define NTHR 256
#define NSTAGE 3

#define STAGE_BYTES 32768
#define BIAS_OFF    (NSTAGE * STAGE_BYTES)          // bias AFTER stages
#define SMEM_TOTAL  (BIAS_OFF + 512)
#define CPAD 136

// fused prep grid partition
#define PX_BLOCKS 4096                  // NB*ND/4/256
#define PC_BLOCKS NCK                   // one component per block
#define PREP_BLOCKS (PX_BLOCKS + PC_BLOCKS + 1)

// ---------------- scratch (device globals) ----------------
__device__ __nv_bfloat16 g_Ah[NB * K2];
__device__ __nv_bfloat16 g_Al[NB * K2];
__device__ __nv_bfloat16 g_Bh[NCK * K2];
__device__ __nv_bfloat16 g_Bl[NCK * K2];
__device__ float g_bias[NCK];
__device__ float g_logp[NC];
__device__ float g_cls[NB * NC];

// ---------------- helpers ----------------
__device__ __forceinline__ uint32_t smem_u32(const void* p) {
    uint32_t a;
    asm("{ .reg .u64 t; cvta.to.shared.u64 t, %1; cvt.u32.u64 %0, t; }" : "=r"(a) : "l"(p));
    return a;
}
__device__ __forceinline__ uint32_t swz(uint32_t o) {   // SW128 over 128B rows
    return o ^ (((o >> 7) & 7) << 4);
}
__device__ __forceinline__ void cp16(uint32_t saddr, const void* gaddr) {
    asm volatile("cp.async.cg.shared.global [%0], [%1], 16;" :: "r"(saddr), "l"(gaddr));
}
__device__ __forceinline__ void ldsm4(uint32_t* r, uint32_t addr) {
    asm volatile("ldmatrix.sync.aligned.m8n8.x4.shared.b16 {%0,%1,%2,%3}, [%4];"
        : "=r"(r[0]), "=r"(r[1]), "=r"(r[2]), "=r"(r[3]) : "r"(addr));
}
__device__ __forceinline__ void mma4(float* c, const uint32_t* a, uint32_t b0, uint32_t b1) {
    asm("mma.sync.aligned.m16n8k16.row.col.f32.bf16.bf16.f32 "
        "{%0,%1,%2,%3}, {%4,%5,%6,%7}, {%8,%9}, {%0,%1,%2,%3};"
        : "+f"(c[0]), "+f"(c[1]), "+f"(c[2]), "+f"(c[3])
        : "r"(a[0]), "r"(a[1]), "r"(a[2]), "r"(a[3]), "r"(b0), "r"(b1));
}

// ================= fused prep: x-split | comp-split+bias | priors =================
__global__ void fused_prep_kernel(const float* __restrict__ x,
                                  const float* __restrict__ means,
                                  const float* __restrict__ bw,
                                  const float* __restrict__ weights,
                                  const float* __restrict__ priors) {
    __shared__ float sh[256];
    int bid = blockIdx.x;
    int t = threadIdx.x;

    if (bid < PX_BLOCKS) {
        // ---- A' = [x^2 | x] hi/lo, 4 elems/thread ----
        int i = bid * 256 + t;          // over NB*ND/4, exact
        int b = i >> 7;
        int d4 = (i & 127) * 4;
        float4 v = *(const float4*)(x + (size_t)b * ND + d4);
        float vv[4] = {v.x, v.y, v.z, v.w};
        __nv_bfloat16 h[4], l[4], h2[4], l2[4];
        #pragma unroll
        for (int q = 0; q < 4; q++) {
            float a = vv[q] * vv[q];
            h[q] = __float2bfloat16(a);
            l[q] = __float2bfloat16(a - __bfloat162float(h[q]));
            h2[q] = __float2bfloat16(vv[q]);
            l2[q] = __float2bfloat16(vv[q] - __bfloat162float(h2[q]));
        }
        size_t base = (size_t)b * K2 + d4;
        *(__nv_bfloat162*)(g_Ah + base)     = __nv_bfloat162(h[0], h[1]);
        *(__nv_bfloat162*)(g_Ah + base + 2) = __nv_bfloat162(h[2], h[3]);
        *(__nv_bfloat162*)(g_Al + base)     = __nv_bfloat162(l[0], l[1]);
        *(__nv_bfloat162*)(g_Al + base + 2) = __nv_bfloat162(l[2], l[3]);
        size_t base2 = base + ND;
        *(__nv_bfloat162*)(g_Ah + base2)     = __nv_bfloat162(h2[0], h2[1]);
        *(__nv_bfloat162*)(g_Ah + base2 + 2) = __nv_bfloat162(h2[2], h2[3]);
        *(__nv_bfloat162*)(g_Al + base2)     = __nv_bfloat162(l2[0], l2[1]);
        *(__nv_bfloat162*)(g_Al + base2 + 2) = __nv_bfloat162(l2[2], l2[3]);

    } else if (bid < PX_BLOCKS + PC_BLOCKS) {
        // ---- B' = [invb | -2mu*invb] hi/lo + bias(j), 2 elems/thread ----
        int j = bid - PX_BLOCKS;
        int d2 = t * 2;
        float2 bv2 = *(const float2*)(bw + (size_t)j * ND + d2);
        float2 mu2 = *(const float2*)(means + (size_t)j * ND + d2);
        float bvv[2] = {bv2.x, bv2.y};
        float muv[2] = {mu2.x, mu2.y};
        float ld = 0.f, cj = 0.f;
        __nv_bfloat16 bh[2], bl[2], mh[2], ml[2];
        #pragma unroll
        for (int q = 0; q < 2; q++) {
            float bv = fminf(fmaxf(bvv[q], 1e-6f), 1000.f);
            float inv = 1.0f / bv;
            float m2  = -2.0f * muv[q] * inv;
            bh[q] = __float2bfloat16(inv);
            bl[q] = __float2bfloat16(inv - __bfloat162float(bh[q]));
            mh[q] = __float2bfloat16(m2);
            ml[q] = __float2bfloat16(m2 - __bfloat162float(mh[q]));
            ld += logf(bv);
            cj += muv[q] * muv[q] * inv;
        }
        size_t base = (size_t)j * K2 + d2;
        *(__nv_bfloat162*)(g_Bh + base) = __nv_bfloat162(bh[0], bh[1]);
        *(__nv_bfloat162*)(g_Bl + base) = __nv_bfloat162(bl[0], bl[1]);
        size_t base2 = base + ND;
        *(__nv_bfloat162*)(g_Bh + base2) = __nv_bfloat162(mh[0], mh[1]);
        *(__nv_bfloat162*)(g_Bl + base2) = __nv_bfloat162(ml[0], ml[1]);

        // reduce ld, cj over 256 threads
        #pragma unroll
        for (int o = 16; o > 0; o >>= 1) {
            ld += __shfl_down_sync(0xffffffff, ld, o);
            cj += __shfl_down_sync(0xffffffff, cj, o);
        }
        if ((t & 31) == 0) { sh[t >> 5] = ld; sh[8 + (t >> 5)] = cj; }
        __syncthreads();
        if (t == 0) {
            float LD = 0.f, CJ = 0.f;
            #pragma unroll
            for (int w = 0; w < 8; w++) { LD += sh[w]; CJ += sh[8 + w]; }
            // local class-weight softmax -> logw_j (no cross-block dependency)
            int c = j >> 4, k = j & 15;
            float wv[NK];
            float m = -1e30f;
            #pragma unroll
            for (int q = 0; q < NK; q++) { wv[q] = weights[c * NK + q]; m = fmaxf(m, wv[q]); }
            float s = 0.f;
            #pragma unroll
            for (int q = 0; q < NK; q++) s += expf(wv[q] - m);
            float logw = logf(expf(wv[k] - m) / s + 1e-6f);
            g_bias[j] = -0.5f * (D_LOG_2PI + LD + CJ) + logw;
        }

    } else {
        // ---- priors softmax -> g_logp ----
        float pv = (t < NC) ? priors[t] : -1e30f;
        sh[t] = pv;
        __syncthreads();
        for (int s = 128; s > 0; s >>= 1) { if (t < s) sh[t] = fmaxf(sh[t], sh[t + s]); __syncthreads(); }
        float M = sh[0];
        __syncthreads();
        float e = (t < NC) ? expf(pv - M) : 0.f;
        sh[t] = e;
        __syncthreads();
        for (int s = 128; s > 0; s >>= 1) { if (t < s) sh[t] += sh[t + s]; __syncthreads(); }
        float S = sh[0];
        if (t < NC) g_logp[t] = logf(e / S + 1e-6f);
    }
}

// ---------------- main GEMM (R11 champion, bf16x3, 2 CTAs/SM) ----------------
__global__ void __launch_bounds__(NTHR, 2) gemm_kernel() {
    extern __shared__ char smem[];
    uint32_t sb = smem_u32(smem);
    int tid = threadIdx.x;
    int wid = tid >> 5, lane = tid & 31;
    int rowBase = blockIdx.y * BM;
    int colBase = blockIdx.x * BN;
    float* bias_sm = (float*)(smem + BIAS_OFF);

    if (tid < 128) bias_sm[tid] = g_bias[colBase + tid];

    int wm = (wid & 1) * 64;
    int wn = (wid >> 1) * 32;
    int lrow = lane & 15;
    uint32_t lcol = (uint32_t)((lane >> 4) * 16);

    const __nv_bfloat16* pA[4]; uint32_t sA[4];
    const __nv_bfloat16* pB[4]; uint32_t sB[4];
    #pragma unroll
    for (int it = 0; it < 4; it++) {
        int idx = tid + it * NTHR;
        int row = idx >> 3, ch = idx & 7;
        uint32_t goff = (uint32_t)((rowBase + row) * K2 + (ch & 3) * 8);
        pA[it] = (ch < 4 ? g_Ah : g_Al) + goff;
        sA[it] = swz((uint32_t)(row * 128 + ch * 16));
        uint32_t goffB = (uint32_t)((colBase + row) * K2 + (ch & 3) * 8);
        pB[it] = (ch < 4 ? g_Bh : g_Bl) + goffB;
        sB[it] = swz((uint32_t)(row * 128 + ch * 16));
    }

    uint32_t baseA[4], baseB[2];
    #pragma unroll
    for (int mi = 0; mi < 4; mi++) {
        int r = wm + mi * 16 + lrow;
        baseA[mi] = sb + (uint32_t)(r * 128 + ((r & 7) << 4));
    }
    #pragma unroll
    for (int nj = 0; nj < 2; nj++) {
        int r = wn + nj * 16 + lrow;
        baseB[nj] = sb + 16384 + (uint32_t)(r * 128 + ((r & 7) << 4));
    }

    float acc[64];
    #pragma unroll
    for (int i = 0; i < 64; i++) acc[i] = 0.f;

    auto load_stage = [&](int st) {
        uint32_t sa = sb + (uint32_t)st * STAGE_BYTES;
        #pragma unroll
        for (int it = 0; it < 4; it++) {
            cp16(sa + sA[it],          pA[it]);
            cp16(sa + 16384 + sB[it],  pB[it]);
            pA[it] += BK;
            pB[it] += BK;
        }
        asm volatile("cp.async.commit_group;" ::: "memory");
    };

    load_stage(0);
    load_stage(1);

    int st = 0;
    for (int s = 0; s < NSTEPS; s++) {
        if (s < NSTEPS - 2)
            asm volatile("cp.async.wait_group 1;" ::: "memory");
        else
            asm volatile("cp.async.wait_group 0;" ::: "memory");
        __syncthreads();

        uint32_t so = (uint32_t)st * STAGE_BYTES;

        if (s + 2 < NSTEPS) {
            int nst = st + 2; if (nst >= NSTAGE) nst -= NSTAGE;
            load_stage(nst);
        }

        #pragma unroll
        for (int ks = 0; ks < 2; ks++) {
            uint32_t kb = (uint32_t)(ks * 32) + lcol;
            uint32_t kl = kb + 64u;

            uint32_t bh0[4], bh1[4], bl0[4], bl1[4];
            ldsm4(bh0, (baseB[0] + so) ^ kb);
            ldsm4(bh1, (baseB[1] + so) ^ kb);
            ldsm4(bl0, (baseB[0] + so) ^ kl);
            ldsm4(bl1, (baseB[1] + so) ^ kl);

            #pragma unroll
            for (int mi = 0; mi < 4; mi++) {
                float* C = &acc[mi * 16];
                uint32_t ah[4], al[4];
                ldsm4(ah, (baseA[mi] + so) ^ kb);
                mma4(C + 0,  ah, bh0[0], bh0[2]);
                mma4(C + 4,  ah, bh0[1], bh0[3]);
                mma4(C + 8,  ah, bh1[0], bh1[2]);
                mma4(C + 12, ah, bh1[1], bh1[3]);
                ldsm4(al, (baseA[mi] + so) ^ kl);
                mma4(C + 0,  ah, bl0[0], bl0[2]);
                mma4(C + 4,  ah, bl0[1], bl0[3]);
                mma4(C + 8,  ah, bl1[0], bl1[2]);
                mma4(C + 12, ah, bl1[1], bl1[3]);
                mma4(C + 0,  al, bh0[0], bh0[2]);
                mma4(C + 4,  al, bh0[1], bh0[3]);
                mma4(C + 8,  al, bh1[0], bh1[2]);
                mma4(C + 12, al, bh1[1], bh1[3]);
            }
        }
        st++; if (st >= NSTAGE) st = 0;
    }
    __syncthreads();

    // ---- epilogue: stage C to smem (offset 0; bias untouched), fused lse ----
    float* csh = (float*)smem;
    #pragma unroll
    for (int mi = 0; mi < 4; mi++)
        #pragma unroll
        for (int nj = 0; nj < 4; nj++) {
            float* a = &acc[(mi * 4 + nj) * 4];
            int r0 = wm + mi * 16 + (lane >> 2);
            int c0 = wn + nj * 8 + 2 * (lane & 3);
            csh[r0 * CPAD + c0]           = a[0];
            csh[r0 * CPAD + c0 + 1]       = a[1];
            csh[(r0 + 8) * CPAD + c0]     = a[2];
            csh[(r0 + 8) * CPAD + c0 + 1] = a[3];
        }
    __syncthreads();

    #pragma unroll
    for (int i = 0; i < 4; i++) {
        int p = tid + i * NTHR;
        int row = p >> 3, cl = p & 7;
        const float* base = &csh[row * CPAD + cl * 16];
        float4 x0 = *(const float4*)(base + 0);
        float4 x1 = *(const float4*)(base + 4);
        float4 x2 = *(const float4*)(base + 8);
        float4 x3 = *(const float4*)(base + 12);
        float v[16] = {x0.x, x0.y, x0.z, x0.w, x1.x, x1.y, x1.z, x1.w,
                       x2.x, x2.y, x2.z, x2.w, x3.x, x3.y, x3.z, x3.w};
        #pragma unroll
        for (int j = 0; j < 16; j++)
            v[j] = fmaf(-0.5f, v[j], bias_sm[cl * 16 + j]);
        float m = v[0];
        #pragma unroll
        for (int j = 1; j < 16; j++) m = fmaxf(m, v[j]);
        float sum = 0.f;
        #pragma unroll
        for (int j = 0; j < 16; j++) sum += __expf(v[j] - m);
        g_cls[(size_t)(rowBase + row) * NC + (colBase >> 4) + cl] = m + __logf(sum);
    }
}

// ---------------- per-row reduction over classes ----------------
__global__ void reduce_kernel(float* __restrict__ out) {
    __shared__ float sh[256];
    size_t row = blockIdx.x;
    int t = threadIdx.x;
    float lc = -1e30f;
    if (t < NC) lc = g_cls[row * NC + t] + g_logp[t];
    sh[t] = lc;
    __syncthreads();
    for (int s = 128; s > 0; s >>= 1) { if (t < s) sh[t] = fmaxf(sh[t], sh[t + s]); __syncthreads(); }
    float M = sh[0];
    __syncthreads();
    sh[t] = (t < NC) ? __expf(lc - M) : 0.f;
    __syncthreads();
    for (int s = 128; s > 0; s >>= 1) { if (t < s) sh[t] += sh[t + s]; __syncthreads(); }
    float lse = M + __logf(sh[0]);
    if (t < NC) out[row * NC + t] = lc - lse;
}

// ---------------- launch ----------------
extern "C" void kernel_launch(void* const* d_in, const int* in_sizes, int n_in,
                              void* d_out, int out_size) {
    const float* x       = (const float*)d_in[0];
    const float* means   = (const float*)d_in[1];
    const float* bw      = (const float*)d_in[2];
    const float* weights = (const float*)d_in[3];
    const float* priors  = (const float*)d_in[4];
    float* out = (float*)d_out;

    cudaFuncSetAttribute(gemm_kernel, cudaFuncAttributeMaxDynamicSharedMemorySize, SMEM_TOTAL);

    fused_prep_kernel<<<PREP_BLOCKS, 256>>>(x, means, bw, weights, priors);

    dim3 grid(NCK / BN, NB / BM);   // (25, 64)
    gemm_kernel<<<grid, NTHR, SMEM_TOTAL>>>();

    reduce_kernel<<<NB, 256>>>(out);
}